// round 16
// baseline (speedup 1.0000x reference)
#include <cuda_runtime.h>
#include <cstdint>

// Problem constants (fixed by reference: B=32, S=2048, D=512)
#define PB 32
#define PS 2048
#define D4 128              // float4 per (b,s) position

// Scratch: rank per (b,s). rank >= 0 iff mask set; -1 otherwise.
__device__ int g_rank[PB * PS];

// ---------------------------------------------------------------------------
// Kernel 1: per-row rank via ballot/popc scan.
// One block (1024 threads = 32 warps) per row; two passes of 1024 positions.
// ---------------------------------------------------------------------------
__global__ void __launch_bounds__(1024, 1)
rank_scan_kernel(const int* __restrict__ masks)
{
    const int b = blockIdx.x;
    const int* m = masks + (size_t)b * PS;
    int*       r = g_rank + (size_t)b * PS;

    const int t    = threadIdx.x;
    const int lane = t & 31;
    const int w    = t >> 5;                 // 0..31

    __shared__ int warp_cnt[64];
    __shared__ int warp_off[64];

    const int p0 = t;
    const int p1 = t + 1024;
    const int m0 = (m[p0] != 0);
    const int m1 = (m[p1] != 0);

    const unsigned bal0 = __ballot_sync(0xFFFFFFFFu, m0);
    const unsigned bal1 = __ballot_sync(0xFFFFFFFFu, m1);

    if (lane == 0) {
        warp_cnt[w]      = __popc(bal0);
        warp_cnt[w + 32] = __popc(bal1);
    }
    __syncthreads();

    if (w == 0) {
        const int c0 = warp_cnt[lane];
        const int c1 = warp_cnt[lane + 32];

        int incl = c0;
        #pragma unroll
        for (int off = 1; off < 32; off <<= 1) {
            int v = __shfl_up_sync(0xFFFFFFFFu, incl, off);
            if (lane >= off) incl += v;
        }
        const int total0 = __shfl_sync(0xFFFFFFFFu, incl, 31);
        warp_off[lane] = incl - c0;

        int incl1 = c1;
        #pragma unroll
        for (int off = 1; off < 32; off <<= 1) {
            int v = __shfl_up_sync(0xFFFFFFFFu, incl1, off);
            if (lane >= off) incl1 += v;
        }
        warp_off[lane + 32] = total0 + incl1 - c1;
    }
    __syncthreads();

    const unsigned lt = (1u << lane) - 1u;
    const int rank0 = warp_off[w]      + __popc(bal0 & lt);
    const int rank1 = warp_off[w + 32] + __popc(bal1 & lt);

    r[p0] = m0 ? rank0 : -1;
    r[p1] = m1 ? rank1 : -1;
}

// ---------------------------------------------------------------------------
// Kernel 2 (measured-best config): out = seqs + (rank >= 0 ? pe[rank] : 0).
// 256 threads/block, 2 float4/thread; front-issues the streaming seqs loads
// BEFORE cudaGridDependencySynchronize() so they overlap the scan kernel;
// __ldcs/__stcs keep the 256 MiB of touch-once traffic from evicting the
// 4 MiB pe table in L2.
// ---------------------------------------------------------------------------
__global__ void __launch_bounds__(256, 8)
pe_add_kernel(const float4* __restrict__ seqs,
              const float4* __restrict__ pe,
              float4*       __restrict__ out)
{
    const unsigned t    = threadIdx.x;
    const unsigned idx0 = blockIdx.x * 512u + t;       // element 0
    const unsigned idx1 = idx0 + 256u;                 // element 1

    // Front-issue streaming loads — independent of the primary kernel.
    float4 v0 = __ldcs(seqs + idx0);
    float4 v1 = __ldcs(seqs + idx1);

    // Wait for the scan kernel (architected, memory-ordered).
    cudaGridDependencySynchronize();

    const int r0 = g_rank[idx0 >> 7];
    const int r1 = g_rank[idx1 >> 7];

    if (r0 >= 0) {
        const float4 p = __ldg(pe + (unsigned)r0 * D4 + (idx0 & 127u));
        v0.x += p.x; v0.y += p.y; v0.z += p.z; v0.w += p.w;
    }
    if (r1 >= 0) {
        const float4 p = __ldg(pe + (unsigned)r1 * D4 + (idx1 & 127u));
        v1.x += p.x; v1.y += p.y; v1.z += p.z; v1.w += p.w;
    }

    __stcs(out + idx0, v0);
    __stcs(out + idx1, v1);
}

// ---------------------------------------------------------------------------
// Launch: scan normally, pe_add via PDL so it overlaps the scan.
// Inputs (metadata order): seqs [B,S,D] f32, masks [B,S] int32, pe [2048,D] f32
// Output: [B,S,D] f32
// ---------------------------------------------------------------------------
extern "C" void kernel_launch(void* const* d_in, const int* in_sizes, int n_in,
                              void* d_out, int out_size)
{
    const float* seqs  = (const float*)d_in[0];
    const int*   masks = (const int*)d_in[1];
    const float* pe    = (const float*)d_in[2];
    float*       out   = (float*)d_out;

    (void)in_sizes; (void)n_in; (void)out_size;

    rank_scan_kernel<<<PB, 1024>>>(masks);

    const unsigned total4 = (unsigned)PB * PS * D4;    // 8,388,608

    cudaLaunchConfig_t cfg = {};
    cfg.gridDim  = dim3(total4 / 512, 1, 1);
    cfg.blockDim = dim3(256, 1, 1);
    cfg.dynamicSmemBytes = 0;
    cfg.stream = 0;

    cudaLaunchAttribute attr[1];
    attr[0].id = cudaLaunchAttributeProgrammaticStreamSerialization;
    attr[0].val.programmaticStreamSerializationAllowed = 1;
    cfg.attrs = attr;
    cfg.numAttrs = 1;

    cudaLaunchKernelEx(&cfg, pe_add_kernel,
                       (const float4*)seqs, (const float4*)pe, (float4*)out);
}

// round 17
// speedup vs baseline: 1.0085x; 1.0085x over previous
#include <cuda_runtime.h>
#include <cstdint>

// Problem constants (fixed by reference: B=32, S=2048, D=512)
#define PB 32
#define PS 2048
#define D4 128              // float4 per (b,s) position

// Scratch: rank per (b,s). rank >= 0 iff mask set; -1 otherwise.
__device__ int g_rank[PB * PS];

// ---------------------------------------------------------------------------
// Kernel 1: per-row rank via ballot/popc scan.
// One block (1024 threads = 32 warps) per row; two passes of 1024 positions.
// ---------------------------------------------------------------------------
__global__ void __launch_bounds__(1024, 1)
rank_scan_kernel(const int* __restrict__ masks)
{
    const int b = blockIdx.x;
    const int* m = masks + (size_t)b * PS;
    int*       r = g_rank + (size_t)b * PS;

    const int t    = threadIdx.x;
    const int lane = t & 31;
    const int w    = t >> 5;                 // 0..31

    __shared__ int warp_cnt[64];
    __shared__ int warp_off[64];

    const int p0 = t;
    const int p1 = t + 1024;
    const int m0 = (m[p0] != 0);
    const int m1 = (m[p1] != 0);

    const unsigned bal0 = __ballot_sync(0xFFFFFFFFu, m0);
    const unsigned bal1 = __ballot_sync(0xFFFFFFFFu, m1);

    if (lane == 0) {
        warp_cnt[w]      = __popc(bal0);
        warp_cnt[w + 32] = __popc(bal1);
    }
    __syncthreads();

    if (w == 0) {
        const int c0 = warp_cnt[lane];
        const int c1 = warp_cnt[lane + 32];

        int incl = c0;
        #pragma unroll
        for (int off = 1; off < 32; off <<= 1) {
            int v = __shfl_up_sync(0xFFFFFFFFu, incl, off);
            if (lane >= off) incl += v;
        }
        const int total0 = __shfl_sync(0xFFFFFFFFu, incl, 31);
        warp_off[lane] = incl - c0;

        int incl1 = c1;
        #pragma unroll
        for (int off = 1; off < 32; off <<= 1) {
            int v = __shfl_up_sync(0xFFFFFFFFu, incl1, off);
            if (lane >= off) incl1 += v;
        }
        warp_off[lane + 32] = total0 + incl1 - c1;
    }
    __syncthreads();

    const unsigned lt = (1u << lane) - 1u;
    const int rank0 = warp_off[w]      + __popc(bal0 & lt);
    const int rank1 = warp_off[w + 32] + __popc(bal1 & lt);

    r[p0] = m0 ? rank0 : -1;
    r[p1] = m1 ? rank1 : -1;
}

// ---------------------------------------------------------------------------
// Kernel 2 (measured-best config): out = seqs + (rank >= 0 ? pe[rank] : 0).
// 256 threads/block, 2 float4/thread; front-issues the streaming seqs loads
// BEFORE cudaGridDependencySynchronize() so they overlap the scan kernel;
// __ldcs/__stcs keep the 256 MiB of touch-once traffic from evicting the
// 4 MiB pe table in L2.
// ---------------------------------------------------------------------------
__global__ void __launch_bounds__(256, 8)
pe_add_kernel(const float4* __restrict__ seqs,
              const float4* __restrict__ pe,
              float4*       __restrict__ out)
{
    const unsigned t    = threadIdx.x;
    const unsigned idx0 = blockIdx.x * 512u + t;       // element 0
    const unsigned idx1 = idx0 + 256u;                 // element 1

    // Front-issue streaming loads — independent of the primary kernel.
    float4 v0 = __ldcs(seqs + idx0);
    float4 v1 = __ldcs(seqs + idx1);

    // Wait for the scan kernel (architected, memory-ordered).
    cudaGridDependencySynchronize();

    const int r0 = g_rank[idx0 >> 7];
    const int r1 = g_rank[idx1 >> 7];

    if (r0 >= 0) {
        const float4 p = __ldg(pe + (unsigned)r0 * D4 + (idx0 & 127u));
        v0.x += p.x; v0.y += p.y; v0.z += p.z; v0.w += p.w;
    }
    if (r1 >= 0) {
        const float4 p = __ldg(pe + (unsigned)r1 * D4 + (idx1 & 127u));
        v1.x += p.x; v1.y += p.y; v1.z += p.z; v1.w += p.w;
    }

    __stcs(out + idx0, v0);
    __stcs(out + idx1, v1);
}

// ---------------------------------------------------------------------------
// Launch: scan normally, pe_add via PDL so it overlaps the scan.
// Inputs (metadata order): seqs [B,S,D] f32, masks [B,S] int32, pe [2048,D] f32
// Output: [B,S,D] f32
// ---------------------------------------------------------------------------
extern "C" void kernel_launch(void* const* d_in, const int* in_sizes, int n_in,
                              void* d_out, int out_size)
{
    const float* seqs  = (const float*)d_in[0];
    const int*   masks = (const int*)d_in[1];
    const float* pe    = (const float*)d_in[2];
    float*       out   = (float*)d_out;

    (void)in_sizes; (void)n_in; (void)out_size;

    rank_scan_kernel<<<PB, 1024>>>(masks);

    const unsigned total4 = (unsigned)PB * PS * D4;    // 8,388,608

    cudaLaunchConfig_t cfg = {};
    cfg.gridDim  = dim3(total4 / 512, 1, 1);
    cfg.blockDim = dim3(256, 1, 1);
    cfg.dynamicSmemBytes = 0;
    cfg.stream = 0;

    cudaLaunchAttribute attr[1];
    attr[0].id = cudaLaunchAttributeProgrammaticStreamSerialization;
    attr[0].val.programmaticStreamSerializationAllowed = 1;
    cfg.attrs = attr;
    cfg.numAttrs = 1;

    cudaLaunchKernelEx(&cfg, pe_add_kernel,
                       (const float4*)seqs, (const float4*)pe, (float4*)out);
}